// round 8
// baseline (speedup 1.0000x reference)
#include <cuda_runtime.h>
#include <cuda_bf16.h>
#include <math.h>
#include <stdint.h>

// Problem dims
#define Bsz 256
#define Ssz 128
#define Tsz 64
#define Isz 63
#define Hsz 1024
#define G3  (3*Hsz)   // 3072

// Scratch (device globals — no allocations allowed)
__device__ float g_GI[(size_t)Bsz * Ssz * G3];      // encoder gi_all (B*S, 3H)
__device__ float g_G2[(size_t)Bsz * Tsz * G3];      // decoder gi     (B*T, 3H)
__device__ float g_GH[(size_t)Bsz * G3];            // decoder gh     (B, 3H)
__device__ float g_states[(size_t)Bsz * Tsz * Hsz]; // decoder states (B*T, H)
__device__ float g_hbuf[2][(size_t)Bsz * Hsz];      // hidden fp32, double buffered
__device__ __nv_bfloat16 g_hhi[2][(size_t)Bsz * Hsz];   // h split hi
__device__ __nv_bfloat16 g_hlo[2][(size_t)Bsz * Hsz];   // h split lo
__device__ __nv_bfloat16 g_whh_hi[(size_t)G3 * Hsz];    // Whh split hi
__device__ __nv_bfloat16 g_whh_lo[(size_t)G3 * Hsz];    // Whh split lo

// ---------------------------------------------------------------------------
__device__ __forceinline__ uint32_t smem_u32(const void* p) {
    uint32_t a;
    asm("{ .reg .u64 t; cvta.to.shared.u64 t, %1; cvt.u32.u64 %0, t; }"
        : "=r"(a) : "l"(p));
    return a;
}
__device__ __forceinline__ void cpasync16(uint32_t dst, const void* src) {
    asm volatile("cp.async.cg.shared.global [%0], [%1], 16;"
                 :: "r"(dst), "l"(src) : "memory");
}
#define CP_COMMIT() asm volatile("cp.async.commit_group;" ::: "memory")
#define CP_WAIT(n)  asm volatile("cp.async.wait_group %0;" :: "n"(n) : "memory")

__device__ __forceinline__ void ldsm4(uint32_t* r, uint32_t addr) {
    asm volatile("ldmatrix.sync.aligned.m8n8.x4.shared.b16 {%0,%1,%2,%3}, [%4];"
                 : "=r"(r[0]), "=r"(r[1]), "=r"(r[2]), "=r"(r[3]) : "r"(addr));
}
__device__ __forceinline__ void ldsm2(uint32_t* r, uint32_t addr) {
    asm volatile("ldmatrix.sync.aligned.m8n8.x2.shared.b16 {%0,%1}, [%2];"
                 : "=r"(r[0]), "=r"(r[1]) : "r"(addr));
}
__device__ __forceinline__ void mma_bf16(float* d, const uint32_t* a, const uint32_t* b) {
    asm volatile("mma.sync.aligned.m16n8k16.row.col.f32.bf16.bf16.f32 "
                 "{%0,%1,%2,%3}, {%4,%5,%6,%7}, {%8,%9}, {%0,%1,%2,%3};"
                 : "+f"(d[0]), "+f"(d[1]), "+f"(d[2]), "+f"(d[3])
                 : "r"(a[0]), "r"(a[1]), "r"(a[2]), "r"(a[3]),
                   "r"(b[0]), "r"(b[1]));
}

__device__ __forceinline__ float sigf(float x) { return 1.f / (1.f + expf(-x)); }

// ---------------------------------------------------------------------------
// Warp-MMA fused GRU step, 4-stage cp.async pipeline (3 chunks in flight).
// Grid (64, 2): CTA tile M=128 (batch), N=48 = 16 j x {r,z,n}, K=1024.
// 256 threads = 8 warps as 4m x 2n; warp tile 32 x 24.
// Split-bf16: gh += Ah*Bh + Ah*Bl + Al*Bh  (3x mma).
// Smem rows padded to 80B -> conflict-free ldmatrix.
// ---------------------------------------------------------------------------
#define KC 32
#define NCH (Hsz / KC)         // 32
#define NSTAGE 4
#define AROWB 80
#define OFF_AH 0u
#define OFF_AL 10240u          // 128*80
#define OFF_BH 20480u
#define OFF_BL 24320u          // +48*80
#define STAGE_B 28160u
#define DSMEM (NSTAGE * 28160)
#define GH_STR 52

__global__ __launch_bounds__(256) void gru_step_wm(
    const __nv_bfloat16* __restrict__ hhi,
    const __nv_bfloat16* __restrict__ hlo,
    const float* __restrict__ hprev,
    float*       __restrict__ hout,
    __nv_bfloat16* __restrict__ hhi_out,
    __nv_bfloat16* __restrict__ hlo_out,
    const float* __restrict__ bhh,
    int t)
{
    extern __shared__ __align__(16) char dsmem[];
    const uint32_t sb0 = smem_u32(dsmem);

    const int tid  = threadIdx.x;
    const int wid  = tid >> 5;
    const int lane = tid & 31;
    const int j0   = blockIdx.x << 4;     // 16 j per CTA
    const int m0   = blockIdx.y << 7;     // 128 batch per CTA

    const int wm  = wid & 3;              // 4 m-warps
    const int wn  = wid >> 2;             // 2 n-warps
    const int m0w = wm << 5;              // warp m base (local)
    const int n0w = wn * 24;              // warp n base (local)

    // ldmatrix per-lane address components
    const int lrow = lane & 7;
    const int tsel = lane >> 3;                       // 0..3
    const int arow = ((tsel & 1) << 3) + lrow;        // A row within m16 tile
    const int akof = (tsel >> 1) << 3;                // A k offset (0/8)
    const int brow = lrow;                            // B row within n8 tile
    const int bkof = ((lane >> 3) & 1) << 3;          // B k offset (0/8)

    float acc[2][3][4];
#pragma unroll
    for (int i = 0; i < 2; i++)
#pragma unroll
        for (int j = 0; j < 3; j++)
#pragma unroll
            for (int e = 0; e < 4; e++) acc[i][j][e] = 0.f;

    // ---- chunk loader (cp.async)
    auto load_chunk = [&](int c, int s) {
        const uint32_t sb = sb0 + (uint32_t)s * STAGE_B;
        const int k0 = c * KC;
#pragma unroll
        for (int i = 0; i < 2; i++) {
            const int q = tid + (i << 8);          // 0..511
            const int row = q >> 2, seg = q & 3;
            const size_t src = (size_t)(m0 + row) * Hsz + k0 + seg * 8;
            const uint32_t dst = sb + row * AROWB + seg * 16;
            cpasync16(dst + OFF_AH, hhi + src);
            cpasync16(dst + OFF_AL, hlo + src);
        }
        if (tid < 192) {
            const int row = tid >> 2, seg = tid & 3;   // row 0..47
            const int gate = row >> 4, jj = row & 15;
            const size_t src = ((size_t)gate * Hsz + j0 + jj) * Hsz + k0 + seg * 8;
            const uint32_t dst = sb + row * AROWB + seg * 16;
            cpasync16(dst + OFF_BH, g_whh_hi + src);
            cpasync16(dst + OFF_BL, g_whh_lo + src);
        }
        CP_COMMIT();
    };

    // prologue: fill NSTAGE-1 stages
#pragma unroll
    for (int c = 0; c < NSTAGE - 1; c++) load_chunk(c, c);

    for (int c = 0; c < NCH; c++) {
        const int s = c & (NSTAGE - 1);
        // issue chunk c+NSTAGE-1 into stage (c-1)%NSTAGE (consumed last iter)
        if (c + NSTAGE - 1 < NCH)
            load_chunk(c + NSTAGE - 1, (c + NSTAGE - 1) & (NSTAGE - 1));

        // ensure chunk c has landed (tail-safe wait depth)
        const int rem = NCH - 1 - c;
        if      (rem >= 3) CP_WAIT(3);
        else if (rem == 2) CP_WAIT(2);
        else if (rem == 1) CP_WAIT(1);
        else               CP_WAIT(0);
        __syncthreads();

        const uint32_t sb = sb0 + (uint32_t)s * STAGE_B;
        const uint32_t aH = sb + OFF_AH + (m0w + arow) * AROWB + akof * 2;
        const uint32_t aL = sb + OFF_AL + (m0w + arow) * AROWB + akof * 2;
        const uint32_t bH = sb + OFF_BH + (n0w + brow) * AROWB + bkof * 2;
        const uint32_t bL = sb + OFF_BL + (n0w + brow) * AROWB + bkof * 2;

#pragma unroll
        for (int ks = 0; ks < KC; ks += 16) {
            uint32_t Ah[2][4], Al[2][4], Bh[3][2], Bl[3][2];
#pragma unroll
            for (int i = 0; i < 2; i++) {
                ldsm4(Ah[i], aH + i * (16 * AROWB) + ks * 2);
                ldsm4(Al[i], aL + i * (16 * AROWB) + ks * 2);
            }
#pragma unroll
            for (int j = 0; j < 3; j++) {
                ldsm2(Bh[j], bH + j * (8 * AROWB) + ks * 2);
                ldsm2(Bl[j], bL + j * (8 * AROWB) + ks * 2);
            }
#pragma unroll
            for (int i = 0; i < 2; i++)
#pragma unroll
                for (int j = 0; j < 3; j++) {
                    mma_bf16(acc[i][j], Ah[i], Bh[j]);
                    mma_bf16(acc[i][j], Ah[i], Bl[j]);
                    mma_bf16(acc[i][j], Al[i], Bh[j]);
                }
        }
        __syncthreads();
    }

    // ---- dump accumulators to smem (reuse stage memory), padded stride
    float* ghs = reinterpret_cast<float*>(dsmem);
    const int crow = m0w + (lane >> 2);
    const int ccol = n0w + ((lane & 3) << 1);
#pragma unroll
    for (int i = 0; i < 2; i++)
#pragma unroll
        for (int j = 0; j < 3; j++) {
            const int row = crow + (i << 4);
            const int col = ccol + (j << 3);
            *reinterpret_cast<float2*>(&ghs[row * GH_STR + col]) =
                make_float2(acc[i][j][0], acc[i][j][1]);
            *reinterpret_cast<float2*>(&ghs[(row + 8) * GH_STR + col]) =
                make_float2(acc[i][j][2], acc[i][j][3]);
        }
    __syncthreads();

    // ---- GRU gates: 2048 (m, jj) pairs, 8 per thread
#pragma unroll
    for (int it = 0; it < 8; it++) {
        const int flat = tid + (it << 8);
        const int m  = flat >> 4;
        const int jj = flat & 15;
        const int j  = j0 + jj;
        const int gm = m0 + m;

        const float ghr = ghs[m * GH_STR + jj]       + bhh[j];
        const float ghz = ghs[m * GH_STR + 16 + jj]  + bhh[Hsz + j];
        const float ghn = ghs[m * GH_STR + 32 + jj]  + bhh[2 * Hsz + j];

        const float* gi = g_GI + ((size_t)gm * Ssz + t) * G3;
        const float r  = sigf(gi[j] + ghr);
        const float z  = sigf(gi[Hsz + j] + ghz);
        const float nn = tanhf(gi[2 * Hsz + j] + r * ghn);
        const float hp = hprev[(size_t)gm * Hsz + j];
        const float hv = (1.f - z) * nn + z * hp;

        hout[(size_t)gm * Hsz + j] = hv;
        const __nv_bfloat16 hi = __float2bfloat16_rn(hv);
        hhi_out[(size_t)gm * Hsz + j] = hi;
        hlo_out[(size_t)gm * Hsz + j] =
            __float2bfloat16_rn(hv - __bfloat162float(hi));
    }
}

// ---------------------------------------------------------------------------
// Split Whh into bf16 hi/lo once per run
__global__ void split_whh_kernel(const float* __restrict__ Whh)
{
    const size_t idx = (size_t)blockIdx.x * blockDim.x + threadIdx.x;
    const float w = Whh[idx];
    const __nv_bfloat16 hi = __float2bfloat16_rn(w);
    g_whh_hi[idx] = hi;
    g_whh_lo[idx] = __float2bfloat16_rn(w - __bfloat162float(hi));
}

__global__ void zero_h_kernel()
{
    const int idx = blockIdx.x * blockDim.x + threadIdx.x;
    g_hbuf[0][idx] = 0.f;
    g_hhi[0][idx] = __float2bfloat16(0.f);
    g_hlo[0][idx] = __float2bfloat16(0.f);
}

// ---------------------------------------------------------------------------
// Generic tiled SGEMM with bias (parallel GEMMs: GI, G2, GH, projector)
// ---------------------------------------------------------------------------
__global__ __launch_bounds__(256) void sgemm_bias(
    const float* __restrict__ A, int lda,
    const float* __restrict__ W,
    const float* __restrict__ bias,
    float* __restrict__ C,
    int N, int K)
{
    __shared__ float As[16][64];
    __shared__ float Bsh[16][64];

    const int tid  = threadIdx.x;
    const int tx   = tid & 15;
    const int ty   = tid >> 4;
    const int row0 = blockIdx.y << 6;
    const int col0 = blockIdx.x << 6;

    const int lm = tid >> 2;
    const int lk = (tid & 3) << 2;

    float acc[4][4] = {};

    for (int k0 = 0; k0 < K; k0 += 16) {
#pragma unroll
        for (int c = 0; c < 4; c++) {
            const int k = k0 + lk + c;
            As[lk + c][lm] = (k < K) ? A[(size_t)(row0 + lm) * lda + k] : 0.f;
            const int n = col0 + lm;
            Bsh[lk + c][lm] = (k < K && n < N) ? W[(size_t)n * K + k] : 0.f;
        }
        __syncthreads();

#pragma unroll
        for (int k = 0; k < 16; k++) {
            const float4 av = *reinterpret_cast<const float4*>(&As[k][ty << 2]);
            const float4 bv = *reinterpret_cast<const float4*>(&Bsh[k][tx << 2]);
            const float a[4] = {av.x, av.y, av.z, av.w};
            const float b[4] = {bv.x, bv.y, bv.z, bv.w};
#pragma unroll
            for (int i = 0; i < 4; i++)
#pragma unroll
                for (int j = 0; j < 4; j++)
                    acc[i][j] = fmaf(a[i], b[j], acc[i][j]);
        }
        __syncthreads();
    }

#pragma unroll
    for (int i = 0; i < 4; i++) {
        const int m = row0 + (ty << 2) + i;
#pragma unroll
        for (int j = 0; j < 4; j++) {
            const int n = col0 + (tx << 2) + j;
            if (n < N)
                C[(size_t)m * N + n] = acc[i][j] + bias[n];
        }
    }
}

// Decoder gates: every timestep uses the same enc_h and the same gh row.
__global__ void gates_dec_kernel(const float* __restrict__ hfin)
{
    const size_t idx = (size_t)blockIdx.x * blockDim.x + threadIdx.x;
    const int j  = (int)(idx & (Hsz - 1));
    const int bt = (int)(idx >> 10);
    const int b  = bt >> 6;
    const float* gi = g_G2 + (size_t)bt * G3;
    const float* gh = g_GH + (size_t)b * G3;

    const float r  = sigf(gi[j]          + gh[j]);
    const float z  = sigf(gi[Hsz + j]    + gh[Hsz + j]);
    const float nn = tanhf(gi[2*Hsz + j] + r * gh[2*Hsz + j]);
    const float hp = hfin[(size_t)b * Hsz + j];
    g_states[idx] = (1.f - z) * nn + z * hp;
}

// ---------------------------------------------------------------------------
extern "C" void kernel_launch(void* const* d_in, const int* in_sizes, int n_in,
                              void* d_out, int out_size)
{
    const float* enc_in  = (const float*)d_in[0];
    const float* dec_in  = (const float*)d_in[1];
    const float* enc_Wih = (const float*)d_in[2];
    const float* enc_Whh = (const float*)d_in[3];
    const float* enc_bih = (const float*)d_in[4];
    const float* enc_bhh = (const float*)d_in[5];
    const float* dec_Wih = (const float*)d_in[6];
    const float* dec_Whh = (const float*)d_in[7];
    const float* dec_bih = (const float*)d_in[8];
    const float* dec_bhh = (const float*)d_in[9];
    const float* proj_W  = (const float*)d_in[10];
    const float* proj_b  = (const float*)d_in[11];
    float* out = (float*)d_out;

    // Opt in to >48KB dynamic smem for the MMA step kernel.
    cudaFuncSetAttribute(gru_step_wm,
                         cudaFuncAttributeMaxDynamicSharedMemorySize, DSMEM);

    float *GI, *G2, *GH, *states, *hbuf;
    __nv_bfloat16 *hhi, *hlo;
    cudaGetSymbolAddress((void**)&GI,     g_GI);
    cudaGetSymbolAddress((void**)&G2,     g_G2);
    cudaGetSymbolAddress((void**)&GH,     g_GH);
    cudaGetSymbolAddress((void**)&states, g_states);
    cudaGetSymbolAddress((void**)&hbuf,   g_hbuf);
    cudaGetSymbolAddress((void**)&hhi,    g_hhi);
    cudaGetSymbolAddress((void**)&hlo,    g_hlo);
    float* h0 = hbuf;
    float* h1 = hbuf + (size_t)Bsz * Hsz;
    __nv_bfloat16* hhi0 = hhi; __nv_bfloat16* hhi1 = hhi + (size_t)Bsz * Hsz;
    __nv_bfloat16* hlo0 = hlo; __nv_bfloat16* hlo1 = hlo + (size_t)Bsz * Hsz;

    const dim3 blk256(256);

    zero_h_kernel<<<(Bsz * Hsz) / 256, blk256>>>();
    split_whh_kernel<<<(int)(((size_t)G3 * Hsz) / 256), blk256>>>(enc_Whh);

    // Encoder input gates for ALL timesteps
    sgemm_bias<<<dim3(G3 / 64, (Bsz * Ssz) / 64), blk256>>>(
        enc_in, Isz, enc_Wih, enc_bih, GI, G3, Isz);

    // Encoder recurrence: 128 sequential warp-MMA steps
    for (int t = 0; t < Ssz; t++) {
        const int s = t & 1;
        gru_step_wm<<<dim3(Hsz / 16, Bsz / 128), blk256, DSMEM>>>(
            s ? hhi1 : hhi0, s ? hlo1 : hlo0, s ? h1 : h0,
            s ? h0 : h1,     s ? hhi0 : hhi1, s ? hlo0 : hlo1,
            enc_bhh, t);
    }
    float* enc_h = h0;   // 128 steps (even) -> buffer 0

    // Decoder hidden-side gates (shared by all T timesteps)
    sgemm_bias<<<dim3(G3 / 64, Bsz / 64), blk256>>>(
        enc_h, Hsz, dec_Whh, dec_bhh, GH, G3, Hsz);

    // Decoder input-side gates for all timesteps
    sgemm_bias<<<dim3(G3 / 64, (Bsz * Tsz) / 64), blk256>>>(
        dec_in, Isz, dec_Wih, dec_bih, G2, G3, Isz);

    // Decoder gates -> states (B*T, H)
    gates_dec_kernel<<<(int)(((size_t)Bsz * Tsz * Hsz) / 256), blk256>>>(enc_h);

    // Projector: out (B*T, I) = states @ proj_W^T + proj_b
    sgemm_bias<<<dim3((Isz + 63) / 64, (Bsz * Tsz) / 64), blk256>>>(
        states, Hsz, proj_W, proj_b, out, Isz, Hsz);
}

// round 9
// speedup vs baseline: 1.2281x; 1.2281x over previous
#include <cuda_runtime.h>
#include <cuda_bf16.h>
#include <math.h>
#include <stdint.h>

// Problem dims
#define Bsz 256
#define Ssz 128
#define Tsz 64
#define Isz 63
#define Hsz 1024
#define G3  (3*Hsz)   // 3072

// Scratch (device globals — no allocations allowed)
__device__ float g_GI[(size_t)Bsz * Ssz * G3];      // encoder gi_all (B*S, 3H)
__device__ float g_G2[(size_t)Bsz * Tsz * G3];      // decoder gi     (B*T, 3H)
__device__ float g_GH[(size_t)Bsz * G3];            // decoder gh     (B, 3H)
__device__ float g_states[(size_t)Bsz * Tsz * Hsz]; // decoder states (B*T, H)
__device__ float g_hbuf[2][(size_t)Bsz * Hsz];      // hidden fp32, double buffered
__device__ __nv_bfloat16 g_hhi[2][(size_t)Bsz * Hsz];   // h split hi
__device__ __nv_bfloat16 g_hlo[2][(size_t)Bsz * Hsz];   // h split lo
__device__ __nv_bfloat16 g_whh_hi[(size_t)G3 * Hsz];    // Whh split hi
__device__ __nv_bfloat16 g_whh_lo[(size_t)G3 * Hsz];    // Whh split lo

// ---------------------------------------------------------------------------
__device__ __forceinline__ uint32_t smem_u32(const void* p) {
    uint32_t a;
    asm("{ .reg .u64 t; cvta.to.shared.u64 t, %1; cvt.u32.u64 %0, t; }"
        : "=r"(a) : "l"(p));
    return a;
}
__device__ __forceinline__ void cpasync16(uint32_t dst, const void* src) {
    asm volatile("cp.async.cg.shared.global [%0], [%1], 16;"
                 :: "r"(dst), "l"(src) : "memory");
}
#define CP_COMMIT() asm volatile("cp.async.commit_group;" ::: "memory")
#define CP_WAIT(n)  asm volatile("cp.async.wait_group %0;" :: "n"(n) : "memory")

__device__ __forceinline__ void ldsm4(uint32_t* r, uint32_t addr) {
    asm volatile("ldmatrix.sync.aligned.m8n8.x4.shared.b16 {%0,%1,%2,%3}, [%4];"
                 : "=r"(r[0]), "=r"(r[1]), "=r"(r[2]), "=r"(r[3]) : "r"(addr));
}
__device__ __forceinline__ void ldsm2(uint32_t* r, uint32_t addr) {
    asm volatile("ldmatrix.sync.aligned.m8n8.x2.shared.b16 {%0,%1}, [%2];"
                 : "=r"(r[0]), "=r"(r[1]) : "r"(addr));
}
__device__ __forceinline__ void mma_bf16(float* d, const uint32_t* a, const uint32_t* b) {
    asm volatile("mma.sync.aligned.m16n8k16.row.col.f32.bf16.bf16.f32 "
                 "{%0,%1,%2,%3}, {%4,%5,%6,%7}, {%8,%9}, {%0,%1,%2,%3};"
                 : "+f"(d[0]), "+f"(d[1]), "+f"(d[2]), "+f"(d[3])
                 : "r"(a[0]), "r"(a[1]), "r"(a[2]), "r"(a[3]),
                   "r"(b[0]), "r"(b[1]));
}

__device__ __forceinline__ float sigf(float x) { return 1.f / (1.f + expf(-x)); }

// ---------------------------------------------------------------------------
// Warp-MMA fused GRU step, v2:
//  - CTA tile M=64 (grid 64 x 4 = 256 CTAs -> 2 CTAs/SM for cross-CTA overlap)
//  - ONE barrier per chunk (wait -> sync -> issue-next -> compute)
//  - split accumulators (main Ah*Bh vs corrections Ah*Bl + Al*Bh) for 2x ILP
// 256 threads = 8 warps as 4m x 2n; warp tile 16 x 24.
// 4-stage cp.async pipeline, 3 chunks in flight.
// Smem rows padded to 80B -> conflict-free ldmatrix.
// ---------------------------------------------------------------------------
#define KC 32
#define NCH (Hsz / KC)         // 32
#define NSTAGE 4
#define AROWB 80
#define OFF_AH 0u
#define OFF_AL 5120u           // 64*80
#define OFF_BH 10240u
#define OFF_BL 14080u          // +48*80
#define STAGE_B 17920u
#define DSMEM (NSTAGE * 17920) // 71680
#define GH_STR 52

__global__ __launch_bounds__(256) void gru_step_wm(
    const __nv_bfloat16* __restrict__ hhi,
    const __nv_bfloat16* __restrict__ hlo,
    const float* __restrict__ hprev,
    float*       __restrict__ hout,
    __nv_bfloat16* __restrict__ hhi_out,
    __nv_bfloat16* __restrict__ hlo_out,
    const float* __restrict__ bhh,
    int t)
{
    extern __shared__ __align__(16) char dsmem[];
    const uint32_t sb0 = smem_u32(dsmem);

    const int tid  = threadIdx.x;
    const int wid  = tid >> 5;
    const int lane = tid & 31;
    const int j0   = blockIdx.x << 4;     // 16 j per CTA
    const int m0   = blockIdx.y << 6;     // 64 batch per CTA

    const int wm  = wid & 3;              // 4 m-warps (16 rows each)
    const int wn  = wid >> 2;             // 2 n-warps (24 cols each)
    const int m0w = wm << 4;              // warp m base (local)
    const int n0w = wn * 24;              // warp n base (local)

    // ldmatrix per-lane address components
    const int lrow = lane & 7;
    const int tsel = lane >> 3;                       // 0..3
    const int arow = ((tsel & 1) << 3) + lrow;        // A row within m16 tile
    const int akof = (tsel >> 1) << 3;                // A k offset (0/8)
    const int brow = lrow;                            // B row within n8 tile
    const int bkof = ((lane >> 3) & 1) << 3;          // B k offset (0/8)

    // split accumulators: accM = Ah*Bh, accC = Ah*Bl + Al*Bh
    float accM[3][4], accC[3][4];
#pragma unroll
    for (int j = 0; j < 3; j++)
#pragma unroll
        for (int e = 0; e < 4; e++) { accM[j][e] = 0.f; accC[j][e] = 0.f; }

    // ---- chunk loader (cp.async): A 64x32 (hi+lo), B 48x32 (hi+lo)
    auto load_chunk = [&](int c, int s) {
        const uint32_t sb = sb0 + (uint32_t)s * STAGE_B;
        const int k0 = c * KC;
        {
            const int row = tid >> 2, seg = tid & 3;   // 64 rows x 4 segs
            const size_t src = (size_t)(m0 + row) * Hsz + k0 + seg * 8;
            const uint32_t dst = sb + row * AROWB + seg * 16;
            cpasync16(dst + OFF_AH, hhi + src);
            cpasync16(dst + OFF_AL, hlo + src);
        }
        if (tid < 192) {
            const int row = tid >> 2, seg = tid & 3;   // 48 rows x 4 segs
            const int gate = row >> 4, jj = row & 15;
            const size_t src = ((size_t)gate * Hsz + j0 + jj) * Hsz + k0 + seg * 8;
            const uint32_t dst = sb + row * AROWB + seg * 16;
            cpasync16(dst + OFF_BH, g_whh_hi + src);
            cpasync16(dst + OFF_BL, g_whh_lo + src);
        }
        CP_COMMIT();
    };

    // prologue: 3 chunks in flight
#pragma unroll
    for (int c = 0; c < NSTAGE - 1; c++) load_chunk(c, c);

    for (int c = 0; c < NCH; c++) {
        const int s = c & (NSTAGE - 1);
        const int rem = NCH - 1 - c;
        if      (rem >= 2) CP_WAIT(2);
        else if (rem == 1) CP_WAIT(1);
        else               CP_WAIT(0);
        __syncthreads();   // publishes chunk c; proves compute c-1 done

        if (c + NSTAGE - 1 < NCH)
            load_chunk(c + NSTAGE - 1, (c + NSTAGE - 1) & (NSTAGE - 1));

        const uint32_t sb = sb0 + (uint32_t)s * STAGE_B;
        const uint32_t aH = sb + OFF_AH + (m0w + arow) * AROWB + akof * 2;
        const uint32_t aL = sb + OFF_AL + (m0w + arow) * AROWB + akof * 2;
        const uint32_t bH = sb + OFF_BH + (n0w + brow) * AROWB + bkof * 2;
        const uint32_t bL = sb + OFF_BL + (n0w + brow) * AROWB + bkof * 2;

#pragma unroll
        for (int ks = 0; ks < KC; ks += 16) {
            uint32_t Ah[4], Al[4], Bh[3][2], Bl[3][2];
            ldsm4(Ah, aH + ks * 2);
            ldsm4(Al, aL + ks * 2);
#pragma unroll
            for (int j = 0; j < 3; j++) {
                ldsm2(Bh[j], bH + j * (8 * AROWB) + ks * 2);
                ldsm2(Bl[j], bL + j * (8 * AROWB) + ks * 2);
            }
#pragma unroll
            for (int j = 0; j < 3; j++) {
                mma_bf16(accM[j], Ah, Bh[j]);
                mma_bf16(accC[j], Ah, Bl[j]);
                mma_bf16(accC[j], Al, Bh[j]);
            }
        }
        // no trailing barrier: next iteration's top barrier protects stage reuse
    }
    __syncthreads();   // all compute done before reusing smem for epilogue

    // ---- dump accumulators (main + corrections) to smem, padded stride
    float* ghs = reinterpret_cast<float*>(dsmem);
    const int crow = m0w + (lane >> 2);
    const int ccol = n0w + ((lane & 3) << 1);
#pragma unroll
    for (int j = 0; j < 3; j++) {
        const int col = ccol + (j << 3);
        *reinterpret_cast<float2*>(&ghs[crow * GH_STR + col]) =
            make_float2(accM[j][0] + accC[j][0], accM[j][1] + accC[j][1]);
        *reinterpret_cast<float2*>(&ghs[(crow + 8) * GH_STR + col]) =
            make_float2(accM[j][2] + accC[j][2], accM[j][3] + accC[j][3]);
    }
    __syncthreads();

    // ---- GRU gates: 1024 (m, jj) pairs, 4 per thread
#pragma unroll
    for (int it = 0; it < 4; it++) {
        const int flat = tid + (it << 8);
        const int m  = flat >> 4;
        const int jj = flat & 15;
        const int j  = j0 + jj;
        const int gm = m0 + m;

        const float ghr = ghs[m * GH_STR + jj]       + bhh[j];
        const float ghz = ghs[m * GH_STR + 16 + jj]  + bhh[Hsz + j];
        const float ghn = ghs[m * GH_STR + 32 + jj]  + bhh[2 * Hsz + j];

        const float* gi = g_GI + ((size_t)gm * Ssz + t) * G3;
        const float r  = sigf(gi[j] + ghr);
        const float z  = sigf(gi[Hsz + j] + ghz);
        const float nn = tanhf(gi[2 * Hsz + j] + r * ghn);
        const float hp = hprev[(size_t)gm * Hsz + j];
        const float hv = (1.f - z) * nn + z * hp;

        hout[(size_t)gm * Hsz + j] = hv;
        const __nv_bfloat16 hi = __float2bfloat16_rn(hv);
        hhi_out[(size_t)gm * Hsz + j] = hi;
        hlo_out[(size_t)gm * Hsz + j] =
            __float2bfloat16_rn(hv - __bfloat162float(hi));
    }
}

// ---------------------------------------------------------------------------
// Split Whh into bf16 hi/lo once per run
__global__ void split_whh_kernel(const float* __restrict__ Whh)
{
    const size_t idx = (size_t)blockIdx.x * blockDim.x + threadIdx.x;
    const float w = Whh[idx];
    const __nv_bfloat16 hi = __float2bfloat16_rn(w);
    g_whh_hi[idx] = hi;
    g_whh_lo[idx] = __float2bfloat16_rn(w - __bfloat162float(hi));
}

__global__ void zero_h_kernel()
{
    const int idx = blockIdx.x * blockDim.x + threadIdx.x;
    g_hbuf[0][idx] = 0.f;
    g_hhi[0][idx] = __float2bfloat16(0.f);
    g_hlo[0][idx] = __float2bfloat16(0.f);
}

// ---------------------------------------------------------------------------
// Generic tiled SGEMM with bias (parallel GEMMs: GI, G2, GH, projector)
// ---------------------------------------------------------------------------
__global__ __launch_bounds__(256) void sgemm_bias(
    const float* __restrict__ A, int lda,
    const float* __restrict__ W,
    const float* __restrict__ bias,
    float* __restrict__ C,
    int N, int K)
{
    __shared__ float As[16][64];
    __shared__ float Bsh[16][64];

    const int tid  = threadIdx.x;
    const int tx   = tid & 15;
    const int ty   = tid >> 4;
    const int row0 = blockIdx.y << 6;
    const int col0 = blockIdx.x << 6;

    const int lm = tid >> 2;
    const int lk = (tid & 3) << 2;

    float acc[4][4] = {};

    for (int k0 = 0; k0 < K; k0 += 16) {
#pragma unroll
        for (int c = 0; c < 4; c++) {
            const int k = k0 + lk + c;
            As[lk + c][lm] = (k < K) ? A[(size_t)(row0 + lm) * lda + k] : 0.f;
            const int n = col0 + lm;
            Bsh[lk + c][lm] = (k < K && n < N) ? W[(size_t)n * K + k] : 0.f;
        }
        __syncthreads();

#pragma unroll
        for (int k = 0; k < 16; k++) {
            const float4 av = *reinterpret_cast<const float4*>(&As[k][ty << 2]);
            const float4 bv = *reinterpret_cast<const float4*>(&Bsh[k][tx << 2]);
            const float a[4] = {av.x, av.y, av.z, av.w};
            const float b[4] = {bv.x, bv.y, bv.z, bv.w};
#pragma unroll
            for (int i = 0; i < 4; i++)
#pragma unroll
                for (int j = 0; j < 4; j++)
                    acc[i][j] = fmaf(a[i], b[j], acc[i][j]);
        }
        __syncthreads();
    }

#pragma unroll
    for (int i = 0; i < 4; i++) {
        const int m = row0 + (ty << 2) + i;
#pragma unroll
        for (int j = 0; j < 4; j++) {
            const int n = col0 + (tx << 2) + j;
            if (n < N)
                C[(size_t)m * N + n] = acc[i][j] + bias[n];
        }
    }
}

// Decoder gates: every timestep uses the same enc_h and the same gh row.
__global__ void gates_dec_kernel(const float* __restrict__ hfin)
{
    const size_t idx = (size_t)blockIdx.x * blockDim.x + threadIdx.x;
    const int j  = (int)(idx & (Hsz - 1));
    const int bt = (int)(idx >> 10);
    const int b  = bt >> 6;
    const float* gi = g_G2 + (size_t)bt * G3;
    const float* gh = g_GH + (size_t)b * G3;

    const float r  = sigf(gi[j]          + gh[j]);
    const float z  = sigf(gi[Hsz + j]    + gh[Hsz + j]);
    const float nn = tanhf(gi[2*Hsz + j] + r * gh[2*Hsz + j]);
    const float hp = hfin[(size_t)b * Hsz + j];
    g_states[idx] = (1.f - z) * nn + z * hp;
}

// ---------------------------------------------------------------------------
extern "C" void kernel_launch(void* const* d_in, const int* in_sizes, int n_in,
                              void* d_out, int out_size)
{
    const float* enc_in  = (const float*)d_in[0];
    const float* dec_in  = (const float*)d_in[1];
    const float* enc_Wih = (const float*)d_in[2];
    const float* enc_Whh = (const float*)d_in[3];
    const float* enc_bih = (const float*)d_in[4];
    const float* enc_bhh = (const float*)d_in[5];
    const float* dec_Wih = (const float*)d_in[6];
    const float* dec_Whh = (const float*)d_in[7];
    const float* dec_bih = (const float*)d_in[8];
    const float* dec_bhh = (const float*)d_in[9];
    const float* proj_W  = (const float*)d_in[10];
    const float* proj_b  = (const float*)d_in[11];
    float* out = (float*)d_out;

    // Opt in to >48KB dynamic smem for the MMA step kernel.
    cudaFuncSetAttribute(gru_step_wm,
                         cudaFuncAttributeMaxDynamicSharedMemorySize, DSMEM);

    float *GI, *G2, *GH, *states, *hbuf;
    __nv_bfloat16 *hhi, *hlo;
    cudaGetSymbolAddress((void**)&GI,     g_GI);
    cudaGetSymbolAddress((void**)&G2,     g_G2);
    cudaGetSymbolAddress((void**)&GH,     g_GH);
    cudaGetSymbolAddress((void**)&states, g_states);
    cudaGetSymbolAddress((void**)&hbuf,   g_hbuf);
    cudaGetSymbolAddress((void**)&hhi,    g_hhi);
    cudaGetSymbolAddress((void**)&hlo,    g_hlo);
    float* h0 = hbuf;
    float* h1 = hbuf + (size_t)Bsz * Hsz;
    __nv_bfloat16* hhi0 = hhi; __nv_bfloat16* hhi1 = hhi + (size_t)Bsz * Hsz;
    __nv_bfloat16* hlo0 = hlo; __nv_bfloat16* hlo1 = hlo + (size_t)Bsz * Hsz;

    const dim3 blk256(256);

    zero_h_kernel<<<(Bsz * Hsz) / 256, blk256>>>();
    split_whh_kernel<<<(int)(((size_t)G3 * Hsz) / 256), blk256>>>(enc_Whh);

    // Encoder input gates for ALL timesteps
    sgemm_bias<<<dim3(G3 / 64, (Bsz * Ssz) / 64), blk256>>>(
        enc_in, Isz, enc_Wih, enc_bih, GI, G3, Isz);

    // Encoder recurrence: 128 sequential warp-MMA steps
    for (int t = 0; t < Ssz; t++) {
        const int s = t & 1;
        gru_step_wm<<<dim3(Hsz / 16, Bsz / 64), blk256, DSMEM>>>(
            s ? hhi1 : hhi0, s ? hlo1 : hlo0, s ? h1 : h0,
            s ? h0 : h1,     s ? hhi0 : hhi1, s ? hlo0 : hlo1,
            enc_bhh, t);
    }
    float* enc_h = h0;   // 128 steps (even) -> buffer 0

    // Decoder hidden-side gates (shared by all T timesteps)
    sgemm_bias<<<dim3(G3 / 64, Bsz / 64), blk256>>>(
        enc_h, Hsz, dec_Whh, dec_bhh, GH, G3, Hsz);

    // Decoder input-side gates for all timesteps
    sgemm_bias<<<dim3(G3 / 64, (Bsz * Tsz) / 64), blk256>>>(
        dec_in, Isz, dec_Wih, dec_bih, G2, G3, Isz);

    // Decoder gates -> states (B*T, H)
    gates_dec_kernel<<<(int)(((size_t)Bsz * Tsz * Hsz) / 256), blk256>>>(enc_h);

    // Projector: out (B*T, I) = states @ proj_W^T + proj_b
    sgemm_bias<<<dim3((Isz + 63) / 64, (Bsz * Tsz) / 64), blk256>>>(
        states, Hsz, proj_W, proj_b, out, Isz, Hsz);
}

// round 10
// speedup vs baseline: 1.2557x; 1.0225x over previous
#include <cuda_runtime.h>
#include <cuda_bf16.h>
#include <math.h>
#include <stdint.h>

// Problem dims
#define Bsz 256
#define Ssz 128
#define Tsz 64
#define Isz 63
#define Hsz 1024
#define G3  (3*Hsz)   // 3072

// Scratch (device globals — no allocations allowed)
__device__ float g_GI[(size_t)Bsz * Ssz * G3];      // encoder gi_all (B*S, 3H)
__device__ float g_G2[(size_t)Bsz * Tsz * G3];      // decoder gi     (B*T, 3H)
__device__ float g_GH[(size_t)Bsz * G3];            // decoder gh     (B, 3H)
__device__ float g_states[(size_t)Bsz * Tsz * Hsz]; // decoder states (B*T, H)
__device__ float g_hbuf[2][(size_t)Bsz * Hsz];      // hidden fp32, double buffered
__device__ __nv_bfloat16 g_hhi[2][(size_t)Bsz * Hsz];   // h split hi
__device__ __nv_bfloat16 g_hlo[2][(size_t)Bsz * Hsz];   // h split lo
__device__ __nv_bfloat16 g_whh_hi[(size_t)G3 * Hsz];    // Whh split hi
__device__ __nv_bfloat16 g_whh_lo[(size_t)G3 * Hsz];    // Whh split lo

// ---------------------------------------------------------------------------
__device__ __forceinline__ uint32_t smem_u32(const void* p) {
    uint32_t a;
    asm("{ .reg .u64 t; cvta.to.shared.u64 t, %1; cvt.u32.u64 %0, t; }"
        : "=r"(a) : "l"(p));
    return a;
}
__device__ __forceinline__ void cpasync16(uint32_t dst, const void* src) {
    asm volatile("cp.async.cg.shared.global [%0], [%1], 16;"
                 :: "r"(dst), "l"(src) : "memory");
}
#define CP_COMMIT() asm volatile("cp.async.commit_group;" ::: "memory")
#define CP_WAIT(n)  asm volatile("cp.async.wait_group %0;" :: "n"(n) : "memory")

__device__ __forceinline__ void ldsm4(uint32_t* r, uint32_t addr) {
    asm volatile("ldmatrix.sync.aligned.m8n8.x4.shared.b16 {%0,%1,%2,%3}, [%4];"
                 : "=r"(r[0]), "=r"(r[1]), "=r"(r[2]), "=r"(r[3]) : "r"(addr));
}
__device__ __forceinline__ void ldsm2(uint32_t* r, uint32_t addr) {
    asm volatile("ldmatrix.sync.aligned.m8n8.x2.shared.b16 {%0,%1}, [%2];"
                 : "=r"(r[0]), "=r"(r[1]) : "r"(addr));
}
__device__ __forceinline__ void mma_bf16(float* d, const uint32_t* a, const uint32_t* b) {
    asm volatile("mma.sync.aligned.m16n8k16.row.col.f32.bf16.bf16.f32 "
                 "{%0,%1,%2,%3}, {%4,%5,%6,%7}, {%8,%9}, {%0,%1,%2,%3};"
                 : "+f"(d[0]), "+f"(d[1]), "+f"(d[2]), "+f"(d[3])
                 : "r"(a[0]), "r"(a[1]), "r"(a[2]), "r"(a[3]),
                   "r"(b[0]), "r"(b[1]));
}

__device__ __forceinline__ float sigf(float x) { return 1.f / (1.f + expf(-x)); }

// ---------------------------------------------------------------------------
// Warp-MMA fused GRU step, v3:
//  - CTA tile M=32, N=48; 128 threads = 4 warps as 2m x 2n (warp tile 16x24)
//  - grid (64 j, 8 m) = 512 CTAs -> ~3.5 CTAs/SM for deep cross-CTA overlap
//  - ONE barrier per chunk; split accumulators (main vs correction)
//  - epilogue operands (gi, hprev) prefetched into registers at kernel start
// 4-stage cp.async pipeline (stage 12.8KB, total 51.2KB).
// Smem rows padded to 80B -> conflict-free ldmatrix.
// ---------------------------------------------------------------------------
#define KC 32
#define NCH (Hsz / KC)         // 32
#define NSTAGE 4
#define AROWB 80
#define OFF_AH 0u
#define OFF_AL 2560u           // 32*80
#define OFF_BH 5120u
#define OFF_BL 8960u           // +48*80
#define STAGE_B 12800u
#define DSMEM (NSTAGE * 12800) // 51200
#define GH_STR 52

__global__ __launch_bounds__(128) void gru_step_wm(
    const __nv_bfloat16* __restrict__ hhi,
    const __nv_bfloat16* __restrict__ hlo,
    const float* __restrict__ hprev,
    float*       __restrict__ hout,
    __nv_bfloat16* __restrict__ hhi_out,
    __nv_bfloat16* __restrict__ hlo_out,
    const float* __restrict__ bhh,
    int t)
{
    extern __shared__ __align__(16) char dsmem[];
    const uint32_t sb0 = smem_u32(dsmem);

    const int tid  = threadIdx.x;
    const int wid  = tid >> 5;
    const int lane = tid & 31;
    const int j0   = blockIdx.x << 4;     // 16 j per CTA
    const int m0   = blockIdx.y << 5;     // 32 batch per CTA

    const int wm  = wid & 1;              // 2 m-warps (16 rows each)
    const int wn  = wid >> 1;             // 2 n-warps (24 cols each)
    const int m0w = wm << 4;              // warp m base (local)
    const int n0w = wn * 24;              // warp n base (local)

    // ---- epilogue operand prefetch (DRAM latency hidden behind mainloop)
    float pgr[4], pgz[4], pgn[4], php[4];
#pragma unroll
    for (int it = 0; it < 4; it++) {
        const int flat = tid + (it << 7);        // 0..511
        const int m  = flat >> 4;
        const int jj = flat & 15;
        const int gm = m0 + m;
        const float* gi = g_GI + ((size_t)gm * Ssz + t) * G3 + j0 + jj;
        pgr[it] = gi[0];
        pgz[it] = gi[Hsz];
        pgn[it] = gi[2 * Hsz];
        php[it] = hprev[(size_t)gm * Hsz + j0 + jj];
    }

    // ldmatrix per-lane address components
    const int lrow = lane & 7;
    const int tsel = lane >> 3;                       // 0..3
    const int arow = ((tsel & 1) << 3) + lrow;        // A row within m16 tile
    const int akof = (tsel >> 1) << 3;                // A k offset (0/8)
    const int brow = lrow;                            // B row within n8 tile
    const int bkof = ((lane >> 3) & 1) << 3;          // B k offset (0/8)

    // split accumulators: accM = Ah*Bh, accC = Ah*Bl + Al*Bh
    float accM[3][4], accC[3][4];
#pragma unroll
    for (int j = 0; j < 3; j++)
#pragma unroll
        for (int e = 0; e < 4; e++) { accM[j][e] = 0.f; accC[j][e] = 0.f; }

    // ---- chunk loader (cp.async): A 32x32 (hi+lo), B 48x32 (hi+lo)
    auto load_chunk = [&](int c, int s) {
        const uint32_t sb = sb0 + (uint32_t)s * STAGE_B;
        const int k0 = c * KC;
        {
            const int row = tid >> 2, seg = tid & 3;   // 32 rows x 4 segs
            const size_t src = (size_t)(m0 + row) * Hsz + k0 + seg * 8;
            const uint32_t dst = sb + row * AROWB + seg * 16;
            cpasync16(dst + OFF_AH, hhi + src);
            cpasync16(dst + OFF_AL, hlo + src);
        }
#pragma unroll
        for (int i = 0; i < 2; i++) {
            const int task = tid + (i << 7);           // 0..255
            if (task < 192) {
                const int row = task >> 2, seg = task & 3;   // 48 rows x 4 segs
                const int gate = row >> 4, jj = row & 15;
                const size_t src = ((size_t)gate * Hsz + j0 + jj) * Hsz + k0 + seg * 8;
                const uint32_t dst = sb + row * AROWB + seg * 16;
                cpasync16(dst + OFF_BH, g_whh_hi + src);
                cpasync16(dst + OFF_BL, g_whh_lo + src);
            }
        }
        CP_COMMIT();
    };

    // prologue: 3 chunks in flight
#pragma unroll
    for (int c = 0; c < NSTAGE - 1; c++) load_chunk(c, c);

    for (int c = 0; c < NCH; c++) {
        const int s = c & (NSTAGE - 1);
        const int rem = NCH - 1 - c;
        if      (rem >= 2) CP_WAIT(2);
        else if (rem == 1) CP_WAIT(1);
        else               CP_WAIT(0);
        __syncthreads();   // publishes chunk c; proves compute c-1 done

        if (c + NSTAGE - 1 < NCH)
            load_chunk(c + NSTAGE - 1, (c + NSTAGE - 1) & (NSTAGE - 1));

        const uint32_t sb = sb0 + (uint32_t)s * STAGE_B;
        const uint32_t aH = sb + OFF_AH + (m0w + arow) * AROWB + akof * 2;
        const uint32_t aL = sb + OFF_AL + (m0w + arow) * AROWB + akof * 2;
        const uint32_t bH = sb + OFF_BH + (n0w + brow) * AROWB + bkof * 2;
        const uint32_t bL = sb + OFF_BL + (n0w + brow) * AROWB + bkof * 2;

#pragma unroll
        for (int ks = 0; ks < KC; ks += 16) {
            uint32_t Ah[4], Al[4], Bh[3][2], Bl[3][2];
            ldsm4(Ah, aH + ks * 2);
            ldsm4(Al, aL + ks * 2);
#pragma unroll
            for (int j = 0; j < 3; j++) {
                ldsm2(Bh[j], bH + j * (8 * AROWB) + ks * 2);
                ldsm2(Bl[j], bL + j * (8 * AROWB) + ks * 2);
            }
#pragma unroll
            for (int j = 0; j < 3; j++) {
                mma_bf16(accM[j], Ah, Bh[j]);
                mma_bf16(accC[j], Ah, Bl[j]);
                mma_bf16(accC[j], Al, Bh[j]);
            }
        }
        // no trailing barrier: next iteration's top barrier protects stage reuse
    }
    __syncthreads();   // all compute done before reusing smem for epilogue

    // ---- dump accumulators (main + corrections) to smem, padded stride
    float* ghs = reinterpret_cast<float*>(dsmem);
    const int crow = m0w + (lane >> 2);
    const int ccol = n0w + ((lane & 3) << 1);
#pragma unroll
    for (int j = 0; j < 3; j++) {
        const int col = ccol + (j << 3);
        *reinterpret_cast<float2*>(&ghs[crow * GH_STR + col]) =
            make_float2(accM[j][0] + accC[j][0], accM[j][1] + accC[j][1]);
        *reinterpret_cast<float2*>(&ghs[(crow + 8) * GH_STR + col]) =
            make_float2(accM[j][2] + accC[j][2], accM[j][3] + accC[j][3]);
    }
    __syncthreads();

    // ---- GRU gates: 512 (m, jj) pairs, 4 per thread (operands prefetched)
#pragma unroll
    for (int it = 0; it < 4; it++) {
        const int flat = tid + (it << 7);
        const int m  = flat >> 4;
        const int jj = flat & 15;
        const int j  = j0 + jj;
        const int gm = m0 + m;

        const float ghr = ghs[m * GH_STR + jj]       + bhh[j];
        const float ghz = ghs[m * GH_STR + 16 + jj]  + bhh[Hsz + j];
        const float ghn = ghs[m * GH_STR + 32 + jj]  + bhh[2 * Hsz + j];

        const float r  = sigf(pgr[it] + ghr);
        const float z  = sigf(pgz[it] + ghz);
        const float nn = tanhf(pgn[it] + r * ghn);
        const float hv = (1.f - z) * nn + z * php[it];

        hout[(size_t)gm * Hsz + j] = hv;
        const __nv_bfloat16 hi = __float2bfloat16_rn(hv);
        hhi_out[(size_t)gm * Hsz + j] = hi;
        hlo_out[(size_t)gm * Hsz + j] =
            __float2bfloat16_rn(hv - __bfloat162float(hi));
    }
}

// ---------------------------------------------------------------------------
// Split Whh into bf16 hi/lo once per run
__global__ void split_whh_kernel(const float* __restrict__ Whh)
{
    const size_t idx = (size_t)blockIdx.x * blockDim.x + threadIdx.x;
    const float w = Whh[idx];
    const __nv_bfloat16 hi = __float2bfloat16_rn(w);
    g_whh_hi[idx] = hi;
    g_whh_lo[idx] = __float2bfloat16_rn(w - __bfloat162float(hi));
}

__global__ void zero_h_kernel()
{
    const int idx = blockIdx.x * blockDim.x + threadIdx.x;
    g_hbuf[0][idx] = 0.f;
    g_hhi[0][idx] = __float2bfloat16(0.f);
    g_hlo[0][idx] = __float2bfloat16(0.f);
}

// ---------------------------------------------------------------------------
// Generic tiled SGEMM with bias (parallel GEMMs: GI, G2, GH, projector)
// ---------------------------------------------------------------------------
__global__ __launch_bounds__(256) void sgemm_bias(
    const float* __restrict__ A, int lda,
    const float* __restrict__ W,
    const float* __restrict__ bias,
    float* __restrict__ C,
    int N, int K)
{
    __shared__ float As[16][64];
    __shared__ float Bsh[16][64];

    const int tid  = threadIdx.x;
    const int tx   = tid & 15;
    const int ty   = tid >> 4;
    const int row0 = blockIdx.y << 6;
    const int col0 = blockIdx.x << 6;

    const int lm = tid >> 2;
    const int lk = (tid & 3) << 2;

    float acc[4][4] = {};

    for (int k0 = 0; k0 < K; k0 += 16) {
#pragma unroll
        for (int c = 0; c < 4; c++) {
            const int k = k0 + lk + c;
            As[lk + c][lm] = (k < K) ? A[(size_t)(row0 + lm) * lda + k] : 0.f;
            const int n = col0 + lm;
            Bsh[lk + c][lm] = (k < K && n < N) ? W[(size_t)n * K + k] : 0.f;
        }
        __syncthreads();

#pragma unroll
        for (int k = 0; k < 16; k++) {
            const float4 av = *reinterpret_cast<const float4*>(&As[k][ty << 2]);
            const float4 bv = *reinterpret_cast<const float4*>(&Bsh[k][tx << 2]);
            const float a[4] = {av.x, av.y, av.z, av.w};
            const float b[4] = {bv.x, bv.y, bv.z, bv.w};
#pragma unroll
            for (int i = 0; i < 4; i++)
#pragma unroll
                for (int j = 0; j < 4; j++)
                    acc[i][j] = fmaf(a[i], b[j], acc[i][j]);
        }
        __syncthreads();
    }

#pragma unroll
    for (int i = 0; i < 4; i++) {
        const int m = row0 + (ty << 2) + i;
#pragma unroll
        for (int j = 0; j < 4; j++) {
            const int n = col0 + (tx << 2) + j;
            if (n < N)
                C[(size_t)m * N + n] = acc[i][j] + bias[n];
        }
    }
}

// Decoder gates: every timestep uses the same enc_h and the same gh row.
__global__ void gates_dec_kernel(const float* __restrict__ hfin)
{
    const size_t idx = (size_t)blockIdx.x * blockDim.x + threadIdx.x;
    const int j  = (int)(idx & (Hsz - 1));
    const int bt = (int)(idx >> 10);
    const int b  = bt >> 6;
    const float* gi = g_G2 + (size_t)bt * G3;
    const float* gh = g_GH + (size_t)b * G3;

    const float r  = sigf(gi[j]          + gh[j]);
    const float z  = sigf(gi[Hsz + j]    + gh[Hsz + j]);
    const float nn = tanhf(gi[2*Hsz + j] + r * gh[2*Hsz + j]);
    const float hp = hfin[(size_t)b * Hsz + j];
    g_states[idx] = (1.f - z) * nn + z * hp;
}

// ---------------------------------------------------------------------------
extern "C" void kernel_launch(void* const* d_in, const int* in_sizes, int n_in,
                              void* d_out, int out_size)
{
    const float* enc_in  = (const float*)d_in[0];
    const float* dec_in  = (const float*)d_in[1];
    const float* enc_Wih = (const float*)d_in[2];
    const float* enc_Whh = (const float*)d_in[3];
    const float* enc_bih = (const float*)d_in[4];
    const float* enc_bhh = (const float*)d_in[5];
    const float* dec_Wih = (const float*)d_in[6];
    const float* dec_Whh = (const float*)d_in[7];
    const float* dec_bih = (const float*)d_in[8];
    const float* dec_bhh = (const float*)d_in[9];
    const float* proj_W  = (const float*)d_in[10];
    const float* proj_b  = (const float*)d_in[11];
    float* out = (float*)d_out;

    // Opt in to >48KB dynamic smem for the MMA step kernel.
    cudaFuncSetAttribute(gru_step_wm,
                         cudaFuncAttributeMaxDynamicSharedMemorySize, DSMEM);

    float *GI, *G2, *GH, *states, *hbuf;
    __nv_bfloat16 *hhi, *hlo;
    cudaGetSymbolAddress((void**)&GI,     g_GI);
    cudaGetSymbolAddress((void**)&G2,     g_G2);
    cudaGetSymbolAddress((void**)&GH,     g_GH);
    cudaGetSymbolAddress((void**)&states, g_states);
    cudaGetSymbolAddress((void**)&hbuf,   g_hbuf);
    cudaGetSymbolAddress((void**)&hhi,    g_hhi);
    cudaGetSymbolAddress((void**)&hlo,    g_hlo);
    float* h0 = hbuf;
    float* h1 = hbuf + (size_t)Bsz * Hsz;
    __nv_bfloat16* hhi0 = hhi; __nv_bfloat16* hhi1 = hhi + (size_t)Bsz * Hsz;
    __nv_bfloat16* hlo0 = hlo; __nv_bfloat16* hlo1 = hlo + (size_t)Bsz * Hsz;

    const dim3 blk256(256);

    zero_h_kernel<<<(Bsz * Hsz) / 256, blk256>>>();
    split_whh_kernel<<<(int)(((size_t)G3 * Hsz) / 256), blk256>>>(enc_Whh);

    // Encoder input gates for ALL timesteps
    sgemm_bias<<<dim3(G3 / 64, (Bsz * Ssz) / 64), blk256>>>(
        enc_in, Isz, enc_Wih, enc_bih, GI, G3, Isz);

    // Encoder recurrence: 128 sequential warp-MMA steps
    for (int t = 0; t < Ssz; t++) {
        const int s = t & 1;
        gru_step_wm<<<dim3(Hsz / 16, Bsz / 32), 128, DSMEM>>>(
            s ? hhi1 : hhi0, s ? hlo1 : hlo0, s ? h1 : h0,
            s ? h0 : h1,     s ? hhi0 : hhi1, s ? hlo0 : hlo1,
            enc_bhh, t);
    }
    float* enc_h = h0;   // 128 steps (even) -> buffer 0

    // Decoder hidden-side gates (shared by all T timesteps)
    sgemm_bias<<<dim3(G3 / 64, Bsz / 64), blk256>>>(
        enc_h, Hsz, dec_Whh, dec_bhh, GH, G3, Hsz);

    // Decoder input-side gates for all timesteps
    sgemm_bias<<<dim3(G3 / 64, (Bsz * Tsz) / 64), blk256>>>(
        dec_in, Isz, dec_Wih, dec_bih, G2, G3, Isz);

    // Decoder gates -> states (B*T, H)
    gates_dec_kernel<<<(int)(((size_t)Bsz * Tsz * Hsz) / 256), blk256>>>(enc_h);

    // Projector: out (B*T, I) = states @ proj_W^T + proj_b
    sgemm_bias<<<dim3((Isz + 63) / 64, (Bsz * Tsz) / 64), blk256>>>(
        states, Hsz, proj_W, proj_b, out, Isz, Hsz);
}